// round 10
// baseline (speedup 1.0000x reference)
#include <cuda_runtime.h>
#include <cuda_bf16.h>
#include <cstdint>

// Problem constants (fixed by the dataset)
#define SDIM 2048   // tokens per group
#define MDIM 768    // hidden size
#define HDIM 3072   // intermediate size
#define NEXP 16     // num experts
#define CAP  256    // capacity = 2*S/E
#define GMAX 2      // groups (4*1024 tokens / 2048)
#define KSPLIT 4    // split-K factor for GEMM2 (3072/4 = 768 per slice)

// ---------------- scratch (device globals; no runtime allocation) -----------
__device__ __align__(128) float g_disp[NEXP * GMAX * CAP * MDIM];   // [E][G][C][M]
__device__ __align__(128) float g_h   [NEXP * GMAX * CAP * HDIM];   // [E][G][C][H]
__device__ __align__(128) float g_eoP [KSPLIT * NEXP * GMAX * CAP * MDIM]; // [S][E][G][C][M]
__device__ int   g_e1  [GMAX * SDIM];
__device__ int   g_e2  [GMAX * SDIM];
__device__ int   g_pos1[GMAX * SDIM];                // -1 => dropped
__device__ int   g_pos2[GMAX * SDIM];
__device__ float g_gv1 [GMAX * SDIM];
__device__ float g_gv2 [GMAX * SDIM];
__device__ float g_w1  [GMAX * SDIM];
__device__ float g_w2  [GMAX * SDIM];

// packed 2x fp32 FMA (sm_100+; ptxas-only via PTX — see SASS_QUICKREF FFMA2)
__device__ __forceinline__ void ffma2(unsigned long long& c,
                                      unsigned long long a, unsigned long long b) {
    asm("fma.rn.f32x2 %0, %1, %2, %0;" : "+l"(c) : "l"(a), "l"(b));
}

// ---------------- 1) gating: softmax(x @ wg), top-2 -------------------------
__global__ void gating_kernel(const float* __restrict__ x,
                              const float* __restrict__ wg, int T) {
    int warp = (blockIdx.x * blockDim.x + threadIdx.x) >> 5;
    int lane = threadIdx.x & 31;
    if (warp >= T) return;
    const float* xr = x + (size_t)warp * MDIM;
    float acc[NEXP];
#pragma unroll
    for (int e = 0; e < NEXP; e++) acc[e] = 0.f;
    for (int k = lane; k < MDIM; k += 32) {
        float xv = xr[k];
        const float* w = wg + k * NEXP;
#pragma unroll
        for (int e = 0; e < NEXP; e++) acc[e] += xv * w[e];
    }
#pragma unroll
    for (int e = 0; e < NEXP; e++) {
#pragma unroll
        for (int off = 16; off; off >>= 1)
            acc[e] += __shfl_xor_sync(0xffffffffu, acc[e], off);
    }
    if (lane == 0) {
        float mx = acc[0];
#pragma unroll
        for (int e = 1; e < NEXP; e++) mx = fmaxf(mx, acc[e]);
        float p[NEXP], sum = 0.f;
#pragma unroll
        for (int e = 0; e < NEXP; e++) { p[e] = expf(acc[e] - mx); sum += p[e]; }
        float inv = 1.f / sum;
        int e1 = 0; float b1 = p[0];
#pragma unroll
        for (int e = 1; e < NEXP; e++) if (p[e] > b1) { b1 = p[e]; e1 = e; }
        int e2 = 0; float b2 = -1.f;
#pragma unroll
        for (int e = 0; e < NEXP; e++)
            if (e != e1 && p[e] > b2) { b2 = p[e]; e2 = e; }
        g_e1[warp] = e1; g_e2[warp] = e2;
        g_gv1[warp] = b1 * inv; g_gv2[warp] = b2 * inv;
    }
}

// ---------------- 2) capacity scan per group --------------------------------
__global__ void scan_kernel(int G) {
    int g = blockIdx.x;
    int tid = threadIdx.x;
    __shared__ int s_cnt1[NEXP];
    int base = g * SDIM;
    if (tid < NEXP) {
        int cnt = 0;
        for (int s = 0; s < SDIM; s++) {
            if (g_e1[base + s] == tid) {
                int p = cnt++;
                g_pos1[base + s] = (p < CAP) ? p : -1;
            }
        }
        s_cnt1[tid] = cnt < CAP ? cnt : CAP;
    }
    __syncthreads();
    if (tid < NEXP) {
        int cnt = 0, off = s_cnt1[tid];
        for (int s = 0; s < SDIM; s++) {
            if (g_e2[base + s] == tid) {
                int p = cnt++ + off;
                g_pos2[base + s] = (p < CAP) ? p : -1;
            }
        }
    }
    __syncthreads();
    for (int s = tid; s < SDIM; s += blockDim.x) {
        int t = base + s;
        float a = (g_pos1[t] >= 0) ? g_gv1[t] : 0.f;
        float b = (g_pos2[t] >= 0) ? g_gv2[t] : 0.f;
        float den = a + b;
        den = (den > 0.f) ? den : 1.f;
        g_w1[t] = a / den;
        g_w2[t] = b / den;
    }
}

// ---------------- 3) scatter tokens into dispatch buffer --------------------
__global__ void scatter_kernel(const float* __restrict__ x, int G) {
    int t = blockIdx.x;
    int g = t / SDIM;
    const float* xr = x + (size_t)t * MDIM;
    int p1 = g_pos1[t], p2 = g_pos2[t];
    float* d1 = (p1 >= 0) ? g_disp + (((size_t)g_e1[t] * G + g) * CAP + p1) * MDIM : nullptr;
    float* d2 = (p2 >= 0) ? g_disp + (((size_t)g_e2[t] * G + g) * CAP + p2) * MDIM : nullptr;
    for (int m = threadIdx.x; m < MDIM; m += blockDim.x) {
        float v = xr[m];
        if (d1) d1[m] = v;
        if (d2) d2[m] = v;
    }
}

// ---------------- 4/5) SGEMM body: 128x128, K-chunk 16, FFMA2 inner loop -----
// A stored DUPLICATED in SMEM (As[k][2m]=As[k][2m+1]=A[m][k]) so LDS.128 yields
// packed {a,a} operands; B pairs loaded packed; 32 fma.rn.f32x2 per k-thread.
template<bool RELU>
__device__ __forceinline__ void sgemm_body(
    const float* __restrict__ A, const float* __restrict__ B, float* __restrict__ C,
    int K, int lda, int ldb, int ldc) {
    __shared__ float As[2][16][256];   // duplicated: 32 KB
    __shared__ float Bs[2][16][128];   // 16 KB  (total 48 KB = static limit)
    const int tid = threadIdx.x;
    const int arow = tid >> 1, acol = (tid & 1) * 8;   // A loader: 128 rows x 16 k
    const int brow = tid >> 4, bcol = (tid & 15) * 8;  // B loader: 16 k x 128 cols
    const int tx = tid & 15, ty = tid >> 4;            // 16x16 compute threads

    A += (size_t)blockIdx.y * 128 * lda;
    B += (size_t)blockIdx.x * 128;
    C += (size_t)blockIdx.y * 128 * ldc + (size_t)blockIdx.x * 128;

    const float* Arow = A + (size_t)arow * lda + acol;
    const float* Brow0 = B + (size_t)brow * ldb + bcol;

    const int nT = K / 16;

    float4 a0, a1, b0, b1;

    // prologue: chunk 0 -> stage 0
    a0 = *(const float4*)(Arow);
    a1 = *(const float4*)(Arow + 4);
    b0 = *(const float4*)(Brow0);
    b1 = *(const float4*)(Brow0 + 4);
    {
        const float av[8] = { a0.x, a0.y, a0.z, a0.w, a1.x, a1.y, a1.z, a1.w };
#pragma unroll
        for (int j = 0; j < 8; j++) {
            float2 d; d.x = av[j]; d.y = av[j];
            *(float2*)&As[0][acol + j][2 * arow] = d;
        }
        *(float4*)&Bs[0][brow][bcol]     = b0;
        *(float4*)&Bs[0][brow][bcol + 4] = b1;
    }
    __syncthreads();

    unsigned long long acc[8][4];
#pragma unroll
    for (int i = 0; i < 8; i++)
#pragma unroll
        for (int j = 0; j < 4; j++) acc[i][j] = 0ull;

    for (int t = 0; t < nT; t++) {
        if (t + 1 < nT) {
            const float* An = Arow + (t + 1) * 16;
            const float* Bn = Brow0 + (size_t)(t + 1) * 16 * ldb;
            a0 = *(const float4*)(An);
            a1 = *(const float4*)(An + 4);
            b0 = *(const float4*)(Bn);
            b1 = *(const float4*)(Bn + 4);
        }

        const int s = t & 1;
#pragma unroll
        for (int k = 0; k < 16; k++) {
            // A fragments: 4 LDS.128, each = two packed {a,a}; warp-broadcast
            ulonglong2 aA = *(const ulonglong2*)&As[s][k][8 * ty];
            ulonglong2 aB = *(const ulonglong2*)&As[s][k][8 * ty + 4];
            ulonglong2 aC = *(const ulonglong2*)&As[s][k][128 + 8 * ty];
            ulonglong2 aD = *(const ulonglong2*)&As[s][k][128 + 8 * ty + 4];
            // B fragments: 2 LDS.128, each = two packed {b_even, b_odd} pairs
            ulonglong2 bA = *(const ulonglong2*)&Bs[s][k][tx * 4];
            ulonglong2 bB = *(const ulonglong2*)&Bs[s][k][64 + tx * 4];
            unsigned long long av[8] = { aA.x, aA.y, aB.x, aB.y, aC.x, aC.y, aD.x, aD.y };
            unsigned long long bv[4] = { bA.x, bA.y, bB.x, bB.y };
#pragma unroll
            for (int i = 0; i < 8; i++)
#pragma unroll
                for (int j = 0; j < 4; j++)
                    ffma2(acc[i][j], av[i], bv[j]);
        }

        if (t + 1 < nT) {
            const int sn = (t + 1) & 1;
            const float av[8] = { a0.x, a0.y, a0.z, a0.w, a1.x, a1.y, a1.z, a1.w };
#pragma unroll
            for (int j = 0; j < 8; j++) {
                float2 d; d.x = av[j]; d.y = av[j];
                *(float2*)&As[sn][acol + j][2 * arow] = d;
            }
            *(float4*)&Bs[sn][brow][bcol]     = b0;
            *(float4*)&Bs[sn][brow][bcol + 4] = b1;
        }
        __syncthreads();
    }

    // epilogue: acc[i][j] packed over col pairs; rows ty*4+i (+64), cols tx*4 (+64)
#pragma unroll
    for (int ih = 0; ih < 2; ih++) {
#pragma unroll
        for (int i = 0; i < 4; i++) {
            int row = ih * 64 + ty * 4 + i;
            int ii = ih * 4 + i;
            float* cr = C + (size_t)row * ldc;
#pragma unroll
            for (int jh = 0; jh < 2; jh++) {
                float2 p0 = *(float2*)&acc[ii][jh * 2];
                float2 p1 = *(float2*)&acc[ii][jh * 2 + 1];
                float4 v;
                v.x = p0.x; v.y = p0.y; v.z = p1.x; v.w = p1.y;
                if (RELU) {
                    v.x = fmaxf(v.x, 0.f); v.y = fmaxf(v.y, 0.f);
                    v.z = fmaxf(v.z, 0.f); v.w = fmaxf(v.w, 0.f);
                }
                *(float4*)(cr + jh * 64 + tx * 4) = v;
            }
        }
    }
}

// GEMM1: h[e] = relu(disp[e] @ wi[e]),  [G*C,768] @ [768,3072]
__global__ __launch_bounds__(256, 2) void gemm1_kernel(const float* __restrict__ wi, int G) {
    int e = blockIdx.z;
    const float* A = g_disp + (size_t)e * G * CAP * MDIM;
    const float* B = wi + (size_t)e * MDIM * HDIM;
    float* C = g_h + (size_t)e * G * CAP * HDIM;
    sgemm_body<true>(A, B, C, MDIM, MDIM, HDIM, HDIM);
}

// GEMM2 split-K: eoP[s][e] = h[e][:, sK:(s+1)K] @ wo[e][sK:(s+1)K, :]
__global__ __launch_bounds__(256, 2) void gemm2_kernel(const float* __restrict__ wo, int G) {
    int z = blockIdx.z;
    int s = z / NEXP;
    int e = z - s * NEXP;
    const int KS = HDIM / KSPLIT;          // 768 per slice
    const float* A = g_h + (size_t)e * G * CAP * HDIM + (size_t)s * KS;
    const float* B = wo + (size_t)e * HDIM * MDIM + (size_t)s * KS * MDIM;
    float* C = g_eoP + ((size_t)s * NEXP + e) * G * CAP * MDIM;
    sgemm_body<false>(A, B, C, KS, HDIM, MDIM, MDIM);
}

// ---------------- 6) combine (sums split-K partials) -------------------------
__global__ void combine_kernel(float* __restrict__ out, int G) {
    int t = blockIdx.x;
    int g = t / SDIM;
    int p1 = g_pos1[t], p2 = g_pos2[t];
    float w1 = g_w1[t], w2 = g_w2[t];
    const size_t sliceStride = (size_t)NEXP * G * CAP * MDIM;
    const float* r1 = (p1 >= 0) ? g_eoP + (((size_t)g_e1[t] * G + g) * CAP + p1) * MDIM : nullptr;
    const float* r2 = (p2 >= 0) ? g_eoP + (((size_t)g_e2[t] * G + g) * CAP + p2) * MDIM : nullptr;
    float* o = out + (size_t)t * MDIM;
    for (int m = threadIdx.x; m < MDIM; m += blockDim.x) {
        float v = 0.f;
        if (r1) {
            float s1 = 0.f;
#pragma unroll
            for (int s = 0; s < KSPLIT; s++) s1 += r1[s * sliceStride + m];
            v += w1 * s1;
        }
        if (r2) {
            float s2 = 0.f;
#pragma unroll
            for (int s = 0; s < KSPLIT; s++) s2 += r2[s * sliceStride + m];
            v += w2 * s2;
        }
        o[m] = v;
    }
}

// ---------------- launcher --------------------------------------------------
extern "C" void kernel_launch(void* const* d_in, const int* in_sizes, int n_in,
                              void* d_out, int out_size) {
    const float* x  = (const float*)d_in[0];   // [4,1024,768] fp32
    const float* wg = (const float*)d_in[1];   // [768,16]
    const float* wi = (const float*)d_in[2];   // [16,768,3072]
    const float* wo = (const float*)d_in[3];   // [16,3072,768]
    float* out = (float*)d_out;

    int T = in_sizes[0] / MDIM;   // 4096 tokens
    int G = T / SDIM;             // 2 groups
    if (G > GMAX) G = GMAX;
    int Mr = G * CAP;             // 512 rows per expert

    gating_kernel<<<(T + 3) / 4, 128>>>(x, wg, T);
    scan_kernel<<<G, 256>>>(G);
    scatter_kernel<<<T, 256>>>(x, G);
    gemm1_kernel<<<dim3(HDIM / 128, Mr / 128, NEXP), 256>>>(wi, G);
    gemm2_kernel<<<dim3(MDIM / 128, Mr / 128, NEXP * KSPLIT), 256>>>(wo, G);
    combine_kernel<<<T, 256>>>(out, G);
}

// round 11
// speedup vs baseline: 1.2807x; 1.2807x over previous
#include <cuda_runtime.h>
#include <cuda_bf16.h>
#include <cstdint>

// Problem constants (fixed by the dataset)
#define SDIM 2048   // tokens per group
#define MDIM 768    // hidden size
#define HDIM 3072   // intermediate size
#define NEXP 16     // num experts
#define CAP  256    // capacity = 2*S/E
#define GMAX 2      // groups (4*1024 tokens / 2048)
#define KSPLIT 4    // split-K factor for GEMM2 (3072/4 = 768 per slice)

// ---------------- scratch (device globals; no runtime allocation) -----------
__device__ __align__(128) float g_disp[NEXP * GMAX * CAP * MDIM];   // [E][G][C][M]
__device__ __align__(128) float g_h   [NEXP * GMAX * CAP * HDIM];   // [E][G][C][H]
__device__ __align__(128) float g_eoP [KSPLIT * NEXP * GMAX * CAP * MDIM]; // [S][E][G][C][M]
__device__ int   g_e1  [GMAX * SDIM];
__device__ int   g_e2  [GMAX * SDIM];
__device__ int   g_pos1[GMAX * SDIM];                // -1 => dropped
__device__ int   g_pos2[GMAX * SDIM];
__device__ float g_gv1 [GMAX * SDIM];
__device__ float g_gv2 [GMAX * SDIM];
__device__ float g_w1  [GMAX * SDIM];
__device__ float g_w2  [GMAX * SDIM];

// ---------------- 1) gating: softmax(x @ wg), top-2 -------------------------
__global__ void gating_kernel(const float* __restrict__ x,
                              const float* __restrict__ wg, int T) {
    int warp = (blockIdx.x * blockDim.x + threadIdx.x) >> 5;
    int lane = threadIdx.x & 31;
    if (warp >= T) return;
    const float* xr = x + (size_t)warp * MDIM;
    float acc[NEXP];
#pragma unroll
    for (int e = 0; e < NEXP; e++) acc[e] = 0.f;
    for (int k = lane; k < MDIM; k += 32) {
        float xv = xr[k];
        const float* w = wg + k * NEXP;
#pragma unroll
        for (int e = 0; e < NEXP; e++) acc[e] += xv * w[e];
    }
#pragma unroll
    for (int e = 0; e < NEXP; e++) {
#pragma unroll
        for (int off = 16; off; off >>= 1)
            acc[e] += __shfl_xor_sync(0xffffffffu, acc[e], off);
    }
    if (lane == 0) {
        float mx = acc[0];
#pragma unroll
        for (int e = 1; e < NEXP; e++) mx = fmaxf(mx, acc[e]);
        float p[NEXP], sum = 0.f;
#pragma unroll
        for (int e = 0; e < NEXP; e++) { p[e] = expf(acc[e] - mx); sum += p[e]; }
        float inv = 1.f / sum;
        int e1 = 0; float b1 = p[0];
#pragma unroll
        for (int e = 1; e < NEXP; e++) if (p[e] > b1) { b1 = p[e]; e1 = e; }
        int e2 = 0; float b2 = -1.f;
#pragma unroll
        for (int e = 0; e < NEXP; e++)
            if (e != e1 && p[e] > b2) { b2 = p[e]; e2 = e; }
        g_e1[warp] = e1; g_e2[warp] = e2;
        g_gv1[warp] = b1 * inv; g_gv2[warp] = b2 * inv;
    }
}

// ---------------- 2) capacity scan per group (SMEM-staged) -------------------
__global__ void scan_kernel(int G) {
    __shared__ int se1[SDIM];
    __shared__ int se2[SDIM];
    __shared__ int s_cnt1[NEXP];
    int g = blockIdx.x;
    int tid = threadIdx.x;
    int base = g * SDIM;
    for (int s = tid; s < SDIM; s += blockDim.x) {
        se1[s] = g_e1[base + s];
        se2[s] = g_e2[base + s];
    }
    __syncthreads();
    if (tid < NEXP) {
        int cnt = 0;
        for (int s = 0; s < SDIM; s++) {
            if (se1[s] == tid) {
                int p = cnt++;
                g_pos1[base + s] = (p < CAP) ? p : -1;
            }
        }
        s_cnt1[tid] = cnt < CAP ? cnt : CAP;
    }
    __syncthreads();
    if (tid < NEXP) {
        int cnt = 0, off = s_cnt1[tid];
        for (int s = 0; s < SDIM; s++) {
            if (se2[s] == tid) {
                int p = cnt++ + off;
                g_pos2[base + s] = (p < CAP) ? p : -1;
            }
        }
    }
    __syncthreads();
    for (int s = tid; s < SDIM; s += blockDim.x) {
        int t = base + s;
        float a = (g_pos1[t] >= 0) ? g_gv1[t] : 0.f;
        float b = (g_pos2[t] >= 0) ? g_gv2[t] : 0.f;
        float den = a + b;
        den = (den > 0.f) ? den : 1.f;
        g_w1[t] = a / den;
        g_w2[t] = b / den;
    }
}

// ---------------- 3) scatter tokens into dispatch buffer (float4) ------------
__global__ void scatter_kernel(const float* __restrict__ x, int G) {
    int t = blockIdx.x;
    int g = t / SDIM;
    const float4* xr = (const float4*)(x + (size_t)t * MDIM);
    int p1 = g_pos1[t], p2 = g_pos2[t];
    float4* d1 = (p1 >= 0) ? (float4*)(g_disp + (((size_t)g_e1[t] * G + g) * CAP + p1) * MDIM) : nullptr;
    float4* d2 = (p2 >= 0) ? (float4*)(g_disp + (((size_t)g_e2[t] * G + g) * CAP + p2) * MDIM) : nullptr;
    int m = threadIdx.x;            // 192 threads = 192 float4 = 768 floats
    float4 v = xr[m];
    if (d1) d1[m] = v;
    if (d2) d2[m] = v;
}

// ---------------- 4/5) SGEMM body: 128x128 tile, K-chunk 16, double-buffered -
// (byte-identical to the R9 winner)
template<bool RELU>
__device__ __forceinline__ void sgemm_body(
    const float* __restrict__ A, const float* __restrict__ B, float* __restrict__ C,
    int K, int lda, int ldb, int ldc) {
    __shared__ float As[2][16][128];
    __shared__ float Bs[2][16][128];
    const int tid = threadIdx.x;
    const int arow = tid >> 1, acol = (tid & 1) * 8;   // A loader: 128 rows x 16 k
    const int brow = tid >> 4, bcol = (tid & 15) * 8;  // B loader: 16 k x 128 cols
    const int tx = tid & 15, ty = tid >> 4;            // 16x16 compute threads

    A += (size_t)blockIdx.y * 128 * lda;
    B += (size_t)blockIdx.x * 128;
    C += (size_t)blockIdx.y * 128 * ldc + (size_t)blockIdx.x * 128;

    const float* Arow = A + (size_t)arow * lda + acol;
    const float* Brow0 = B + (size_t)brow * ldb + bcol;

    const int nT = K / 16;

    float4 a0, a1, b0, b1;

    a0 = *(const float4*)(Arow);
    a1 = *(const float4*)(Arow + 4);
    b0 = *(const float4*)(Brow0);
    b1 = *(const float4*)(Brow0 + 4);
    {
        As[0][acol + 0][arow] = a0.x; As[0][acol + 1][arow] = a0.y;
        As[0][acol + 2][arow] = a0.z; As[0][acol + 3][arow] = a0.w;
        As[0][acol + 4][arow] = a1.x; As[0][acol + 5][arow] = a1.y;
        As[0][acol + 6][arow] = a1.z; As[0][acol + 7][arow] = a1.w;
        *(float4*)&Bs[0][brow][bcol]     = b0;
        *(float4*)&Bs[0][brow][bcol + 4] = b1;
    }
    __syncthreads();

    float acc[8][8];
#pragma unroll
    for (int i = 0; i < 8; i++)
#pragma unroll
        for (int j = 0; j < 8; j++) acc[i][j] = 0.f;

    for (int t = 0; t < nT; t++) {
        if (t + 1 < nT) {
            const float* An = Arow + (t + 1) * 16;
            const float* Bn = Brow0 + (size_t)(t + 1) * 16 * ldb;
            a0 = *(const float4*)(An);
            a1 = *(const float4*)(An + 4);
            b0 = *(const float4*)(Bn);
            b1 = *(const float4*)(Bn + 4);
        }

        const int s = t & 1;
#pragma unroll
        for (int k = 0; k < 16; k++) {
            float ar[8], br[8];
            *(float4*)&ar[0] = *(const float4*)&As[s][k][ty * 4];
            *(float4*)&ar[4] = *(const float4*)&As[s][k][64 + ty * 4];
            *(float4*)&br[0] = *(const float4*)&Bs[s][k][tx * 4];
            *(float4*)&br[4] = *(const float4*)&Bs[s][k][64 + tx * 4];
#pragma unroll
            for (int i = 0; i < 8; i++)
#pragma unroll
                for (int j = 0; j < 8; j++) acc[i][j] += ar[i] * br[j];
        }

        if (t + 1 < nT) {
            const int sn = (t + 1) & 1;
            As[sn][acol + 0][arow] = a0.x; As[sn][acol + 1][arow] = a0.y;
            As[sn][acol + 2][arow] = a0.z; As[sn][acol + 3][arow] = a0.w;
            As[sn][acol + 4][arow] = a1.x; As[sn][acol + 5][arow] = a1.y;
            As[sn][acol + 6][arow] = a1.z; As[sn][acol + 7][arow] = a1.w;
            *(float4*)&Bs[sn][brow][bcol]     = b0;
            *(float4*)&Bs[sn][brow][bcol + 4] = b1;
        }
        __syncthreads();
    }

#pragma unroll
    for (int ih = 0; ih < 2; ih++) {
#pragma unroll
        for (int i = 0; i < 4; i++) {
            int row = ih * 64 + ty * 4 + i;
            float* cr = C + (size_t)row * ldc;
#pragma unroll
            for (int jh = 0; jh < 2; jh++) {
                float4 v;
                v.x = acc[ih * 4 + i][jh * 4 + 0];
                v.y = acc[ih * 4 + i][jh * 4 + 1];
                v.z = acc[ih * 4 + i][jh * 4 + 2];
                v.w = acc[ih * 4 + i][jh * 4 + 3];
                if (RELU) {
                    v.x = fmaxf(v.x, 0.f); v.y = fmaxf(v.y, 0.f);
                    v.z = fmaxf(v.z, 0.f); v.w = fmaxf(v.w, 0.f);
                }
                *(float4*)(cr + jh * 64 + tx * 4) = v;
            }
        }
    }
}

// GEMM1: h[e] = relu(disp[e] @ wi[e]),  [G*C,768] @ [768,3072]
__global__ __launch_bounds__(256, 2) void gemm1_kernel(const float* __restrict__ wi, int G) {
    int e = blockIdx.z;
    const float* A = g_disp + (size_t)e * G * CAP * MDIM;
    const float* B = wi + (size_t)e * MDIM * HDIM;
    float* C = g_h + (size_t)e * G * CAP * HDIM;
    sgemm_body<true>(A, B, C, MDIM, MDIM, HDIM, HDIM);
}

// GEMM2 split-K: eoP[s][e] = h[e][:, sK:(s+1)K] @ wo[e][sK:(s+1)K, :]
__global__ __launch_bounds__(256, 2) void gemm2_kernel(const float* __restrict__ wo, int G) {
    int z = blockIdx.z;
    int s = z / NEXP;
    int e = z - s * NEXP;
    const int KS = HDIM / KSPLIT;          // 768 per slice
    const float* A = g_h + (size_t)e * G * CAP * HDIM + (size_t)s * KS;
    const float* B = wo + (size_t)e * HDIM * MDIM + (size_t)s * KS * MDIM;
    float* C = g_eoP + ((size_t)s * NEXP + e) * G * CAP * MDIM;
    sgemm_body<false>(A, B, C, KS, HDIM, MDIM, MDIM);
}

// ---------------- 6) combine (sums split-K partials, float4) -----------------
__global__ void combine_kernel(float* __restrict__ out, int G) {
    int t = blockIdx.x;
    int g = t / SDIM;
    int p1 = g_pos1[t], p2 = g_pos2[t];
    float w1 = g_w1[t], w2 = g_w2[t];
    const size_t sliceStride4 = (size_t)NEXP * G * CAP * MDIM / 4;
    const float4* r1 = (p1 >= 0)
        ? (const float4*)(g_eoP + (((size_t)g_e1[t] * G + g) * CAP + p1) * MDIM) : nullptr;
    const float4* r2 = (p2 >= 0)
        ? (const float4*)(g_eoP + (((size_t)g_e2[t] * G + g) * CAP + p2) * MDIM) : nullptr;
    float4* o = (float4*)(out + (size_t)t * MDIM);
    int m = threadIdx.x;            // 192 threads = 768 floats
    float4 v; v.x = v.y = v.z = v.w = 0.f;
    if (r1) {
        float4 s1; s1.x = s1.y = s1.z = s1.w = 0.f;
#pragma unroll
        for (int s = 0; s < KSPLIT; s++) {
            float4 p = r1[s * sliceStride4 + m];
            s1.x += p.x; s1.y += p.y; s1.z += p.z; s1.w += p.w;
        }
        v.x += w1 * s1.x; v.y += w1 * s1.y; v.z += w1 * s1.z; v.w += w1 * s1.w;
    }
    if (r2) {
        float4 s2; s2.x = s2.y = s2.z = s2.w = 0.f;
#pragma unroll
        for (int s = 0; s < KSPLIT; s++) {
            float4 p = r2[s * sliceStride4 + m];
            s2.x += p.x; s2.y += p.y; s2.z += p.z; s2.w += p.w;
        }
        v.x += w2 * s2.x; v.y += w2 * s2.y; v.z += w2 * s2.z; v.w += w2 * s2.w;
    }
    o[m] = v;
}

// ---------------- launcher --------------------------------------------------
extern "C" void kernel_launch(void* const* d_in, const int* in_sizes, int n_in,
                              void* d_out, int out_size) {
    const float* x  = (const float*)d_in[0];   // [4,1024,768] fp32
    const float* wg = (const float*)d_in[1];   // [768,16]
    const float* wi = (const float*)d_in[2];   // [16,768,3072]
    const float* wo = (const float*)d_in[3];   // [16,3072,768]
    float* out = (float*)d_out;

    int T = in_sizes[0] / MDIM;   // 4096 tokens
    int G = T / SDIM;             // 2 groups
    if (G > GMAX) G = GMAX;
    int Mr = G * CAP;             // 512 rows per expert

    gating_kernel<<<(T + 3) / 4, 128>>>(x, wg, T);
    scan_kernel<<<G, 256>>>(G);
    scatter_kernel<<<T, 192>>>(x, G);
    gemm1_kernel<<<dim3(HDIM / 128, Mr / 128, NEXP), 256>>>(wi, G);
    gemm2_kernel<<<dim3(MDIM / 128, Mr / 128, NEXP * KSPLIT), 256>>>(wo, G);
    combine_kernel<<<T, 192>>>(out, G);
}

// round 12
// speedup vs baseline: 1.3260x; 1.0354x over previous
#include <cuda_runtime.h>
#include <cuda_bf16.h>
#include <cstdint>

// Problem constants (fixed by the dataset)
#define SDIM 2048   // tokens per group
#define MDIM 768    // hidden size
#define HDIM 3072   // intermediate size
#define NEXP 16     // num experts
#define CAP  256    // capacity = 2*S/E
#define GMAX 2      // groups (4*1024 tokens / 2048)
#define KSPLIT 4    // split-K factor for GEMM2 (3072/4 = 768 per slice)

// ---------------- scratch (device globals; no runtime allocation) -----------
__device__ __align__(128) float g_disp[NEXP * GMAX * CAP * MDIM];   // [E][G][C][M]
__device__ __align__(128) float g_h   [NEXP * GMAX * CAP * HDIM];   // [E][G][C][H]
__device__ __align__(128) float g_eoP [KSPLIT * NEXP * GMAX * CAP * MDIM]; // [S][E][G][C][M]
__device__ int   g_e1  [GMAX * SDIM];
__device__ int   g_e2  [GMAX * SDIM];
__device__ int   g_pos1[GMAX * SDIM];                // -1 => dropped
__device__ int   g_pos2[GMAX * SDIM];
__device__ float g_gv1 [GMAX * SDIM];
__device__ float g_gv2 [GMAX * SDIM];
__device__ float g_w1  [GMAX * SDIM];
__device__ float g_w2  [GMAX * SDIM];
__device__ int   g_work;          // persistent-GEMM tile queue head
__device__ int   g_done[NEXP];    // per-expert completed gemm1 tiles

// ---------------- 1) gating: softmax(x @ wg), top-2 -------------------------
__global__ void gating_kernel(const float* __restrict__ x,
                              const float* __restrict__ wg, int T) {
    int warp = (blockIdx.x * blockDim.x + threadIdx.x) >> 5;
    int lane = threadIdx.x & 31;
    if (warp >= T) return;
    const float* xr = x + (size_t)warp * MDIM;
    float acc[NEXP];
#pragma unroll
    for (int e = 0; e < NEXP; e++) acc[e] = 0.f;
    for (int k = lane; k < MDIM; k += 32) {
        float xv = xr[k];
        const float* w = wg + k * NEXP;
#pragma unroll
        for (int e = 0; e < NEXP; e++) acc[e] += xv * w[e];
    }
#pragma unroll
    for (int e = 0; e < NEXP; e++) {
#pragma unroll
        for (int off = 16; off; off >>= 1)
            acc[e] += __shfl_xor_sync(0xffffffffu, acc[e], off);
    }
    if (lane == 0) {
        float mx = acc[0];
#pragma unroll
        for (int e = 1; e < NEXP; e++) mx = fmaxf(mx, acc[e]);
        float p[NEXP], sum = 0.f;
#pragma unroll
        for (int e = 0; e < NEXP; e++) { p[e] = expf(acc[e] - mx); sum += p[e]; }
        float inv = 1.f / sum;
        int e1 = 0; float b1 = p[0];
#pragma unroll
        for (int e = 1; e < NEXP; e++) if (p[e] > b1) { b1 = p[e]; e1 = e; }
        int e2 = 0; float b2 = -1.f;
#pragma unroll
        for (int e = 0; e < NEXP; e++)
            if (e != e1 && p[e] > b2) { b2 = p[e]; e2 = e; }
        g_e1[warp] = e1; g_e2[warp] = e2;
        g_gv1[warp] = b1 * inv; g_gv2[warp] = b2 * inv;
    }
}

// ---------------- 2) capacity scan per group (SMEM-staged) + queue reset -----
__global__ void scan_kernel(int G) {
    __shared__ int se1[SDIM];
    __shared__ int se2[SDIM];
    __shared__ int s_cnt1[NEXP];
    int g = blockIdx.x;
    int tid = threadIdx.x;
    int base = g * SDIM;
    if (g == 0) {                      // reset persistent-GEMM queue each launch
        if (tid == 0) g_work = 0;
        if (tid < NEXP) g_done[tid] = 0;
    }
    for (int s = tid; s < SDIM; s += blockDim.x) {
        se1[s] = g_e1[base + s];
        se2[s] = g_e2[base + s];
    }
    __syncthreads();
    if (tid < NEXP) {
        int cnt = 0;
        for (int s = 0; s < SDIM; s++) {
            if (se1[s] == tid) {
                int p = cnt++;
                g_pos1[base + s] = (p < CAP) ? p : -1;
            }
        }
        s_cnt1[tid] = cnt < CAP ? cnt : CAP;
    }
    __syncthreads();
    if (tid < NEXP) {
        int cnt = 0, off = s_cnt1[tid];
        for (int s = 0; s < SDIM; s++) {
            if (se2[s] == tid) {
                int p = cnt++ + off;
                g_pos2[base + s] = (p < CAP) ? p : -1;
            }
        }
    }
    __syncthreads();
    for (int s = tid; s < SDIM; s += blockDim.x) {
        int t = base + s;
        float a = (g_pos1[t] >= 0) ? g_gv1[t] : 0.f;
        float b = (g_pos2[t] >= 0) ? g_gv2[t] : 0.f;
        float den = a + b;
        den = (den > 0.f) ? den : 1.f;
        g_w1[t] = a / den;
        g_w2[t] = b / den;
    }
}

// ---------------- 3) scatter tokens into dispatch buffer (float4) ------------
__global__ void scatter_kernel(const float* __restrict__ x, int G) {
    int t = blockIdx.x;
    int g = t / SDIM;
    const float4* xr = (const float4*)(x + (size_t)t * MDIM);
    int p1 = g_pos1[t], p2 = g_pos2[t];
    float4* d1 = (p1 >= 0) ? (float4*)(g_disp + (((size_t)g_e1[t] * G + g) * CAP + p1) * MDIM) : nullptr;
    float4* d2 = (p2 >= 0) ? (float4*)(g_disp + (((size_t)g_e2[t] * G + g) * CAP + p2) * MDIM) : nullptr;
    int m = threadIdx.x;            // 192 threads = 192 float4 = 768 floats
    float4 v = xr[m];
    if (d1) d1[m] = v;
    if (d2) d2[m] = v;
}

// ---------------- SGEMM tile body (R9/R11-proven, blockIdx -> bx/by) ---------
__device__ void sgemm_tile(
    const float* __restrict__ A, const float* __restrict__ B, float* __restrict__ C,
    int K, int lda, int ldb, int ldc, bool relu, int bx, int by) {
    __shared__ float As[2][16][128];
    __shared__ float Bs[2][16][128];
    const int tid = threadIdx.x;
    const int arow = tid >> 1, acol = (tid & 1) * 8;   // A loader: 128 rows x 16 k
    const int brow = tid >> 4, bcol = (tid & 15) * 8;  // B loader: 16 k x 128 cols
    const int tx = tid & 15, ty = tid >> 4;            // 16x16 compute threads

    A += (size_t)by * 128 * lda;
    B += (size_t)bx * 128;
    C += (size_t)by * 128 * ldc + (size_t)bx * 128;

    const float* Arow = A + (size_t)arow * lda + acol;
    const float* Brow0 = B + (size_t)brow * ldb + bcol;

    const int nT = K / 16;

    float4 a0, a1, b0, b1;

    a0 = *(const float4*)(Arow);
    a1 = *(const float4*)(Arow + 4);
    b0 = *(const float4*)(Brow0);
    b1 = *(const float4*)(Brow0 + 4);
    {
        As[0][acol + 0][arow] = a0.x; As[0][acol + 1][arow] = a0.y;
        As[0][acol + 2][arow] = a0.z; As[0][acol + 3][arow] = a0.w;
        As[0][acol + 4][arow] = a1.x; As[0][acol + 5][arow] = a1.y;
        As[0][acol + 6][arow] = a1.z; As[0][acol + 7][arow] = a1.w;
        *(float4*)&Bs[0][brow][bcol]     = b0;
        *(float4*)&Bs[0][brow][bcol + 4] = b1;
    }
    __syncthreads();

    float acc[8][8];
#pragma unroll
    for (int i = 0; i < 8; i++)
#pragma unroll
        for (int j = 0; j < 8; j++) acc[i][j] = 0.f;

    for (int t = 0; t < nT; t++) {
        if (t + 1 < nT) {
            const float* An = Arow + (t + 1) * 16;
            const float* Bn = Brow0 + (size_t)(t + 1) * 16 * ldb;
            a0 = *(const float4*)(An);
            a1 = *(const float4*)(An + 4);
            b0 = *(const float4*)(Bn);
            b1 = *(const float4*)(Bn + 4);
        }

        const int s = t & 1;
#pragma unroll
        for (int k = 0; k < 16; k++) {
            float ar[8], br[8];
            *(float4*)&ar[0] = *(const float4*)&As[s][k][ty * 4];
            *(float4*)&ar[4] = *(const float4*)&As[s][k][64 + ty * 4];
            *(float4*)&br[0] = *(const float4*)&Bs[s][k][tx * 4];
            *(float4*)&br[4] = *(const float4*)&Bs[s][k][64 + tx * 4];
#pragma unroll
            for (int i = 0; i < 8; i++)
#pragma unroll
                for (int j = 0; j < 8; j++) acc[i][j] += ar[i] * br[j];
        }

        if (t + 1 < nT) {
            const int sn = (t + 1) & 1;
            As[sn][acol + 0][arow] = a0.x; As[sn][acol + 1][arow] = a0.y;
            As[sn][acol + 2][arow] = a0.z; As[sn][acol + 3][arow] = a0.w;
            As[sn][acol + 4][arow] = a1.x; As[sn][acol + 5][arow] = a1.y;
            As[sn][acol + 6][arow] = a1.z; As[sn][acol + 7][arow] = a1.w;
            *(float4*)&Bs[sn][brow][bcol]     = b0;
            *(float4*)&Bs[sn][brow][bcol + 4] = b1;
        }
        __syncthreads();
    }

#pragma unroll
    for (int ih = 0; ih < 2; ih++) {
#pragma unroll
        for (int i = 0; i < 4; i++) {
            int row = ih * 64 + ty * 4 + i;
            float* cr = C + (size_t)row * ldc;
#pragma unroll
            for (int jh = 0; jh < 2; jh++) {
                float4 v;
                v.x = acc[ih * 4 + i][jh * 4 + 0];
                v.y = acc[ih * 4 + i][jh * 4 + 1];
                v.z = acc[ih * 4 + i][jh * 4 + 2];
                v.w = acc[ih * 4 + i][jh * 4 + 3];
                if (relu) {
                    v.x = fmaxf(v.x, 0.f); v.y = fmaxf(v.y, 0.f);
                    v.z = fmaxf(v.z, 0.f); v.w = fmaxf(v.w, 0.f);
                }
                *(float4*)(cr + jh * 64 + tx * 4) = v;
            }
        }
    }
}

// ---------------- 4+5) persistent fused GEMM (work queue + expert gating) ----
__global__ __launch_bounds__(256, 2) void moe_gemm_fused(
    const float* __restrict__ wi, const float* __restrict__ wo, int G)
{
    __shared__ int s_id;
    const int Mr = G * CAP;                         // 512
    const int mT = Mr / 128;                        // 4
    const int t1_per_e = (HDIM / 128) * mT;         // 96
    const int nT1 = NEXP * t1_per_e;                // 1536
    const int t2_per_s = (MDIM / 128) * mT;         // 24
    const int t2_per_e = KSPLIT * t2_per_s;         // 96
    const int nAll = nT1 + NEXP * t2_per_e;         // 3072

    for (;;) {
        if (threadIdx.x == 0) s_id = atomicAdd(&g_work, 1);
        __syncthreads();
        int id = s_id;
        __syncthreads();
        if (id >= nAll) break;

        if (id < nT1) {
            // GEMM1 tile: h[e] = relu(disp[e] @ wi[e])
            int e = id / t1_per_e, r = id % t1_per_e;
            int n = r / mT, m = r % mT;
            const float* A = g_disp + (size_t)e * Mr * MDIM;
            const float* B = wi + (size_t)e * MDIM * HDIM;
            float* C = g_h + (size_t)e * Mr * HDIM;
            sgemm_tile(A, B, C, MDIM, MDIM, HDIM, HDIM, true, n, m);
            __syncthreads();
            if (threadIdx.x == 0) { __threadfence(); atomicAdd(&g_done[e], 1); }
        } else {
            // GEMM2 tile (split-K): gated on expert e's gemm1 completion
            int id2 = id - nT1;
            int e = id2 / t2_per_e, r = id2 % t2_per_e;
            int s = r / t2_per_s, r2 = r % t2_per_s;
            int n = r2 / mT, m = r2 % mT;
            if (threadIdx.x == 0) {
                while (*(volatile int*)&g_done[e] < t1_per_e) __nanosleep(64);
            }
            __syncthreads();
            __threadfence();   // acquire: order g_h reads after observed flag
            const int KS = HDIM / KSPLIT;          // 768 per slice
            const float* A = g_h + (size_t)e * Mr * HDIM + (size_t)s * KS;
            const float* B = wo + (size_t)e * HDIM * MDIM + (size_t)s * KS * MDIM;
            float* C = g_eoP + ((size_t)s * NEXP + e) * Mr * MDIM;
            sgemm_tile(A, B, C, KS, HDIM, MDIM, MDIM, false, n, m);
            __syncthreads();
        }
    }
}

// ---------------- 6) combine (sums split-K partials, float4) -----------------
__global__ void combine_kernel(float* __restrict__ out, int G) {
    int t = blockIdx.x;
    int g = t / SDIM;
    int p1 = g_pos1[t], p2 = g_pos2[t];
    float w1 = g_w1[t], w2 = g_w2[t];
    const size_t sliceStride4 = (size_t)NEXP * G * CAP * MDIM / 4;
    const float4* r1 = (p1 >= 0)
        ? (const float4*)(g_eoP + (((size_t)g_e1[t] * G + g) * CAP + p1) * MDIM) : nullptr;
    const float4* r2 = (p2 >= 0)
        ? (const float4*)(g_eoP + (((size_t)g_e2[t] * G + g) * CAP + p2) * MDIM) : nullptr;
    float4* o = (float4*)(out + (size_t)t * MDIM);
    int m = threadIdx.x;            // 192 threads = 768 floats
    float4 v; v.x = v.y = v.z = v.w = 0.f;
    if (r1) {
        float4 s1; s1.x = s1.y = s1.z = s1.w = 0.f;
#pragma unroll
        for (int s = 0; s < KSPLIT; s++) {
            float4 p = r1[s * sliceStride4 + m];
            s1.x += p.x; s1.y += p.y; s1.z += p.z; s1.w += p.w;
        }
        v.x += w1 * s1.x; v.y += w1 * s1.y; v.z += w1 * s1.z; v.w += w1 * s1.w;
    }
    if (r2) {
        float4 s2; s2.x = s2.y = s2.z = s2.w = 0.f;
#pragma unroll
        for (int s = 0; s < KSPLIT; s++) {
            float4 p = r2[s * sliceStride4 + m];
            s2.x += p.x; s2.y += p.y; s2.z += p.z; s2.w += p.w;
        }
        v.x += w2 * s2.x; v.y += w2 * s2.y; v.z += w2 * s2.z; v.w += w2 * s2.w;
    }
    o[m] = v;
}

// ---------------- launcher --------------------------------------------------
extern "C" void kernel_launch(void* const* d_in, const int* in_sizes, int n_in,
                              void* d_out, int out_size) {
    const float* x  = (const float*)d_in[0];   // [4,1024,768] fp32
    const float* wg = (const float*)d_in[1];   // [768,16]
    const float* wi = (const float*)d_in[2];   // [16,768,3072]
    const float* wo = (const float*)d_in[3];   // [16,3072,768]
    float* out = (float*)d_out;

    int T = in_sizes[0] / MDIM;   // 4096 tokens
    int G = T / SDIM;             // 2 groups
    if (G > GMAX) G = GMAX;

    int dev = 0, sms = 148;
    cudaGetDevice(&dev);
    cudaDeviceGetAttribute(&sms, cudaDevAttrMultiProcessorCount, dev);

    gating_kernel<<<(T + 3) / 4, 128>>>(x, wg, T);
    scan_kernel<<<G, 256>>>(G);
    scatter_kernel<<<T, 192>>>(x, G);
    moe_gemm_fused<<<2 * sms, 256>>>(wi, wo, G);
    combine_kernel<<<T, 192>>>(out, G);
}